// round 1
// baseline (speedup 1.0000x reference)
#include <cuda_runtime.h>
#include <cuda_bf16.h>
#include <cstdint>

// AttentionLayer_50989851738889
//
// Mathematical reduction: the reference computes
//   e = exp(max(g, axis=-1, keepdims=True))        # shape [B, L, 1]
//   a = e / sum(e, axis=-1, keepdims=True)         # sum over size-1 axis -> a = e/e = 1.0 exactly
//   v = a * inputs                                  # == inputs, bit-exact
// g is bounded (|g| <= sum|Wa| ~ 7), so e is finite/positive and x/x == 1.0 in IEEE fp32.
// The output is therefore an exact copy of d_in[0] (B*L*D = 4*1024*512 fp32 = 8 MB).
// Optimal implementation: bandwidth-saturating vectorized copy.

__global__ void copy_kernel_v4(const float4* __restrict__ src,
                               float4* __restrict__ dst,
                               int n4) {
    int i = blockIdx.x * blockDim.x + threadIdx.x;
    int stride = gridDim.x * blockDim.x;
    for (; i < n4; i += stride) {
        dst[i] = src[i];
    }
}

extern "C" void kernel_launch(void* const* d_in, const int* in_sizes, int n_in,
                              void* d_out, int out_size) {
    const float* inputs = (const float*)d_in[0];
    float* out = (float*)d_out;

    // out_size = B*L*D = 2097152, divisible by 4
    int n4 = out_size >> 2;  // 524288 float4 elements

    const int threads = 256;
    int blocks = (n4 + threads - 1) / threads;  // 2048 blocks -> fully occupies 148 SMs
    copy_kernel_v4<<<blocks, threads>>>((const float4*)inputs, (float4*)out, n4);
}

// round 2
// speedup vs baseline: 1.0386x; 1.0386x over previous
#include <cuda_runtime.h>
#include <cuda_bf16.h>
#include <cstdint>

// AttentionLayer_50989851738889
//
// Mathematical reduction (verified bit-exact in R1, rel_err = 0.0):
//   e = exp(max(g, -1, keepdims)); a = e / sum(e, -1, keepdims)  -> sum over
//   size-1 axis == e, so a = e/e = 1.0 exactly (g bounded, e finite nonzero).
//   v = a * inputs == inputs. Output is a copy of d_in[0] (8 MB fp32).
//
// R1 showed the 1-float4-per-thread copy is LATENCY bound (DRAM 17%,
// issue 28%): MLP=1 per thread. This version front-batches 4 independent
// LDG.128 per thread (grid-strided for coalescing), one exact wave:
// 512 blocks x 256 threads x 4 float4 = 524288 = n4.

__global__ void __launch_bounds__(256) copy_kernel_v4x4(
    const float4* __restrict__ src, float4* __restrict__ dst, int n4) {
    const int t = blockIdx.x * blockDim.x + threadIdx.x;
    const int s = gridDim.x * blockDim.x;  // 131072

    // Exact-fit fast path: n4 == 4*s (true for this problem's fixed shape).
    if (4 * s == n4) {
        // 4 independent loads batched up front -> MLP_p1 = 4
        float4 a = src[t];
        float4 b = src[t + s];
        float4 c = src[t + 2 * s];
        float4 d = src[t + 3 * s];
        dst[t]         = a;
        dst[t + s]     = b;
        dst[t + 2 * s] = c;
        dst[t + 3 * s] = d;
    } else {
        // Generic grid-stride fallback (never taken for the fixed shape)
        for (int i = t; i < n4; i += s) dst[i] = src[i];
    }
}

extern "C" void kernel_launch(void* const* d_in, const int* in_sizes, int n_in,
                              void* d_out, int out_size) {
    const float4* src = (const float4*)d_in[0];
    float4* dst = (float4*)d_out;

    int n4 = out_size >> 2;  // 524288 float4

    const int threads = 256;
    const int blocks = 512;  // 512*256*4 == 524288 exactly; single wave
    copy_kernel_v4x4<<<blocks, threads>>>(src, dst, n4);
}